// round 5
// baseline (speedup 1.0000x reference)
#include <cuda_runtime.h>
#include <cuda_bf16.h>
#include <cstdint>

// Problem constants (fixed by the reference)
#define T_ 4096
#define B_ 8
#define F_ 512
#define H_ 1024

#define TM 128   // T-tile (m)
#define TN 128   // H-chunk tile (n)
#define TK 16    // k-step

// smem strides in uint16 units (padded for conflict-free ldmatrix)
#define A_STRIDE 24        // 16 k + 8 pad  -> 48B row stride
#define B_STRIDE 136       // 128 n + 8 pad -> 272B row stride
#define A_ELEMS (TM * A_STRIDE)   // 3072 u16 per part
#define B_ELEMS (TK * B_STRIDE)   // 2176 u16 per part

#define X_ELEMS (T_ * B_ * F_)    // 16,777,216
#define W_ELEMS (B_ * F_ * H_)    //  4,194,304

// bf16 hi/lo scratch (static device globals: the legal scratch mechanism)
__device__ uint16_t g_xh[X_ELEMS];
__device__ uint16_t g_xl[X_ELEMS];
__device__ uint16_t g_wh[W_ELEMS];
__device__ uint16_t g_wl[W_ELEMS];

__device__ __forceinline__ float fix_nan(float v) {
    unsigned u = __float_as_uint(v) & 0x7fffffffu;
    return (u > 0x7f800000u) ? 0.0f : v;
}

__device__ __forceinline__ float bfr(float v) {            // round-to-nearest bf16, back to f32
    return __bfloat162float(__float2bfloat16(v));
}

__device__ __forceinline__ uint32_t f2bf2(float lo, float hi) {  // pack: low half = 'lo'
    uint32_t r;
    asm("cvt.rn.bf16x2.f32 %0, %1, %2;" : "=r"(r) : "f"(hi), "f"(lo));
    return r;
}

__device__ __forceinline__ uint32_t smem_u32(const void* p) {
    uint32_t r;
    asm("{ .reg .u64 t; cvta.to.shared.u64 t, %1; cvt.u32.u64 %0, t; }" : "=r"(r) : "l"(p));
    return r;
}

__device__ __forceinline__ void ldsm4(uint32_t r[4], uint32_t addr) {
    asm volatile("ldmatrix.sync.aligned.m8n8.x4.shared.b16 {%0,%1,%2,%3}, [%4];"
                 : "=r"(r[0]), "=r"(r[1]), "=r"(r[2]), "=r"(r[3]) : "r"(addr));
}

__device__ __forceinline__ void ldsm4t(uint32_t r[4], uint32_t addr) {
    asm volatile("ldmatrix.sync.aligned.m8n8.x4.trans.shared.b16 {%0,%1,%2,%3}, [%4];"
                 : "=r"(r[0]), "=r"(r[1]), "=r"(r[2]), "=r"(r[3]) : "r"(addr));
}

__device__ __forceinline__ void mma_bf16(float c[4],
                                         uint32_t a0, uint32_t a1, uint32_t a2, uint32_t a3,
                                         uint32_t b0, uint32_t b1) {
    asm volatile("mma.sync.aligned.m16n8k16.row.col.f32.bf16.bf16.f32 "
                 "{%0,%1,%2,%3}, {%4,%5,%6,%7}, {%8,%9}, {%0,%1,%2,%3};"
                 : "+f"(c[0]), "+f"(c[1]), "+f"(c[2]), "+f"(c[3])
                 : "r"(a0), "r"(a1), "r"(a2), "r"(a3), "r"(b0), "r"(b1));
}

// ---------------------------------------------------------------------------
// Pre-conversion kernels: fp32 -> (bf16 hi, bf16 lo). Memory-bound.
// ---------------------------------------------------------------------------
__global__ void __launch_bounds__(256)
convert_x_kernel(const float* __restrict__ x)
{
    const size_t i = ((size_t)blockIdx.x * 256 + threadIdx.x) * 4;
    float4 v = *(const float4*)(x + i);
    float a = fix_nan(v.x), bb = fix_nan(v.y), c = fix_nan(v.z), d = fix_nan(v.w);
    float ha = bfr(a), hb = bfr(bb), hc = bfr(c), hd = bfr(d);
    *(uint2*)(g_xh + i) = make_uint2(f2bf2(ha, hb), f2bf2(hc, hd));
    *(uint2*)(g_xl + i) = make_uint2(f2bf2(a - ha, bb - hb), f2bf2(c - hc, d - hd));
}

__global__ void __launch_bounds__(256)
convert_w_kernel(const float* __restrict__ w1)
{
    const size_t i = ((size_t)blockIdx.x * 256 + threadIdx.x) * 4;
    float4 v = *(const float4*)(w1 + i);
    float ha = bfr(v.x), hb = bfr(v.y), hc = bfr(v.z), hd = bfr(v.w);
    *(uint2*)(g_wh + i) = make_uint2(f2bf2(ha, hb), f2bf2(hc, hd));
    *(uint2*)(g_wl + i) = make_uint2(f2bf2(v.x - ha, v.y - hb), f2bf2(v.z - hc, v.w - hd));
}

// ---------------------------------------------------------------------------
// Fused GEMM + epilogue on pre-split bf16 data
// ---------------------------------------------------------------------------
__global__ void __launch_bounds__(256, 2)
mothernet_mma(const float* __restrict__ b1,   // [B, H]
              const float* __restrict__ w2,   // [B, H]
              const float* __restrict__ b2,   // [B]
              float* __restrict__ out)        // [T, B]
{
    // [buf][hi=0/lo=1][...]
    __shared__ __align__(16) uint16_t As[2][2][A_ELEMS];
    __shared__ __align__(16) uint16_t Bs[2][2][B_ELEMS];

    const int b    = blockIdx.y;
    const int t0   = blockIdx.x * TM;
    const int tid  = threadIdx.x;
    const int lane = tid & 31;
    const int wid  = tid >> 5;
    const int wm   = wid >> 2;          // 0..1 : m-slice of 64
    const int wn   = wid & 3;           // 0..3 : n-slice of 32
    const int m0w  = wm * 64;
    const int n0w  = wn * 32;
    const int gid  = lane >> 2;         // 0..7
    const int tig  = lane & 3;          // 0..3

    const float* b1b = b1 + b * H_;
    const float* w2b = w2 + b * H_;

    // gmem->smem loader mapping (256 threads):
    // A: thread -> row tid>>1 (0..127), k-half (tid&1)*8 : one uint4 (8 bf16) per part
    const int aRow = tid >> 1;
    const int aK8  = (tid & 1) * 8;
    // B: thread -> k-row tid>>4 (0..15), n-offset (tid&15)*8 : one uint4 per part
    const int bK   = tid >> 4;
    const int bN8  = (tid & 15) * 8;

    const uint16_t* xh_b = g_xh + ((size_t)(t0 + aRow) * B_ + b) * F_ + aK8;
    const uint16_t* xl_b = g_xl + ((size_t)(t0 + aRow) * B_ + b) * F_ + aK8;
    const uint16_t* wh_b = g_wh + (size_t)b * (F_ * H_) + (size_t)bK * H_ + bN8;
    const uint16_t* wl_b = g_wl + (size_t)b * (F_ * H_) + (size_t)bK * H_ + bN8;

    // ldmatrix per-lane byte offsets
    const uint32_t a_base = smem_u32(&As[0][0][0]);
    const uint32_t b_base = smem_u32(&Bs[0][0][0]);
    const uint32_t aOff = (uint32_t)((m0w + (lane & 15)) * A_STRIDE + ((lane >> 4) * 8)) * 2u;
    const int kB = (lane & 7) + (((lane >> 3) & 1) * 8);
    const uint32_t bOff = (uint32_t)(kB * B_STRIDE + n0w + (((lane >> 4) & 1) * 8)) * 2u;

    float rowsum[8];
#pragma unroll
    for (int i = 0; i < 8; ++i) rowsum[i] = 0.0f;

    auto stash = [&](int buf, const uint4& ah_, const uint4& al_,
                     const uint4& wh_, const uint4& wl_) {
        *(uint4*)&As[buf][0][aRow * A_STRIDE + aK8] = ah_;
        *(uint4*)&As[buf][1][aRow * A_STRIDE + aK8] = al_;
        *(uint4*)&Bs[buf][0][bK * B_STRIDE + bN8]   = wh_;
        *(uint4*)&Bs[buf][1][bK * B_STRIDE + bN8]   = wl_;
    };

    const int NKT = F_ / TK;  // 32

    for (int hc = 0; hc < H_ / TN; ++hc) {
        const int h0 = hc * TN;

        float acc[4][4][4];
#pragma unroll
        for (int mt = 0; mt < 4; ++mt)
#pragma unroll
            for (int nt = 0; nt < 4; ++nt)
#pragma unroll
                for (int c = 0; c < 4; ++c) acc[mt][nt][c] = 0.0f;

        // prologue: chunk 0 -> buf 0
        uint4 pah = *(const uint4*)(xh_b);
        uint4 pal = *(const uint4*)(xl_b);
        uint4 pwh = *(const uint4*)(wh_b + h0);
        uint4 pwl = *(const uint4*)(wl_b + h0);
        stash(0, pah, pal, pwh, pwl);
        __syncthreads();

        for (int kt = 0; kt < NKT; ++kt) {
            const int buf = kt & 1;

            if (kt + 1 < NKT) {   // prefetch next k-chunk into registers
                const int k0 = (kt + 1) * TK;
                pah = *(const uint4*)(xh_b + k0);
                pal = *(const uint4*)(xl_b + k0);
                pwh = *(const uint4*)(wh_b + (size_t)k0 * H_ + h0);
                pwl = *(const uint4*)(wl_b + (size_t)k0 * H_ + h0);
            }

            // ---- fragments + 3-product split MMA ----
            uint32_t ah[4][4], al[4][4];
#pragma unroll
            for (int mt = 0; mt < 4; ++mt) {
                const uint32_t base = a_base + (uint32_t)buf * (2u * A_ELEMS * 2u)
                                    + aOff + (uint32_t)(mt * 16 * A_STRIDE) * 2u;
                ldsm4(ah[mt], base);
                ldsm4(al[mt], base + A_ELEMS * 2u);
            }
#pragma unroll
            for (int np = 0; np < 2; ++np) {
                uint32_t bh[4], bl[4];
                const uint32_t baseb = b_base + (uint32_t)buf * (2u * B_ELEMS * 2u)
                                     + bOff + (uint32_t)np * 32u;
                ldsm4t(bh, baseb);
                ldsm4t(bl, baseb + B_ELEMS * 2u);
#pragma unroll
                for (int half = 0; half < 2; ++half) {
                    const int nt = np * 2 + half;
                    const uint32_t bh0 = bh[half * 2], bh1 = bh[half * 2 + 1];
                    const uint32_t bl0 = bl[half * 2], bl1 = bl[half * 2 + 1];
#pragma unroll
                    for (int mt = 0; mt < 4; ++mt) {
                        mma_bf16(acc[mt][nt], ah[mt][0], ah[mt][1], ah[mt][2], ah[mt][3], bh0, bh1);
                        mma_bf16(acc[mt][nt], ah[mt][0], ah[mt][1], ah[mt][2], ah[mt][3], bl0, bl1);
                        mma_bf16(acc[mt][nt], al[mt][0], al[mt][1], al[mt][2], al[mt][3], bh0, bh1);
                    }
                }
            }

            if (kt + 1 < NKT) stash(buf ^ 1, pah, pal, pwh, pwl);
            __syncthreads();
        }

        // ---- fused epilogue: relu(acc + b1) * w2 -> rowsum ----
#pragma unroll
        for (int nt = 0; nt < 4; ++nt) {
            const int h = h0 + n0w + nt * 8 + tig * 2;
            const float bb0 = __ldg(b1b + h), bb1 = __ldg(b1b + h + 1);
            const float ww0 = __ldg(w2b + h), ww1 = __ldg(w2b + h + 1);
#pragma unroll
            for (int mt = 0; mt < 4; ++mt) {
                rowsum[mt * 2]     += fmaxf(acc[mt][nt][0] + bb0, 0.f) * ww0
                                    + fmaxf(acc[mt][nt][1] + bb1, 0.f) * ww1;
                rowsum[mt * 2 + 1] += fmaxf(acc[mt][nt][2] + bb0, 0.f) * ww0
                                    + fmaxf(acc[mt][nt][3] + bb1, 0.f) * ww1;
            }
        }
    }

    // ---- reduce over n: within warp (tig lanes), then across the 4 n-warps ----
#pragma unroll
    for (int i = 0; i < 8; ++i) {
        rowsum[i] += __shfl_xor_sync(0xffffffffu, rowsum[i], 1);
        rowsum[i] += __shfl_xor_sync(0xffffffffu, rowsum[i], 2);
    }

    float* red = (float*)&As[0][0][0];   // 128 rows x 4 n-warps = 2KB (reuse smem)
    if (tig == 0) {
#pragma unroll
        for (int mt = 0; mt < 4; ++mt) {
            red[(m0w + mt * 16 + gid) * 4 + wn]     = rowsum[mt * 2];
            red[(m0w + mt * 16 + gid + 8) * 4 + wn] = rowsum[mt * 2 + 1];
        }
    }
    __syncthreads();

    if (tid < TM) {
        float s = red[tid * 4] + red[tid * 4 + 1] + red[tid * 4 + 2] + red[tid * 4 + 3] + b2[b];
        out[(size_t)(t0 + tid) * B_ + b] = s;
    }
}

extern "C" void kernel_launch(void* const* d_in, const int* in_sizes, int n_in,
                              void* d_out, int out_size)
{
    (void)in_sizes; (void)n_in; (void)out_size;
    const float* x  = (const float*)d_in[0];
    const float* w1 = (const float*)d_in[1];
    const float* b1 = (const float*)d_in[2];
    const float* w2 = (const float*)d_in[3];
    const float* b2 = (const float*)d_in[4];
    float* out = (float*)d_out;

    convert_x_kernel<<<X_ELEMS / (256 * 4), 256>>>(x);
    convert_w_kernel<<<W_ELEMS / (256 * 4), 256>>>(w1);

    dim3 grid(T_ / TM, B_);   // 32 x 8 = 256 CTAs, 2/SM -> one wave
    mothernet_mma<<<grid, 256>>>(b1, w2, b2, out);
}